// round 5
// baseline (speedup 1.0000x reference)
#include <cuda_runtime.h>

#define DD 128
#define MAXN 100000
#define MAXE 640000

// ---------------- scratch (no allocations allowed) ----------------
__device__ float g_conv[(size_t)MAXN * DD];   // W2 projection, pre-scaled by rsqrt(send_deg)
__device__ float g_agg [(size_t)MAXN * DD];   // scatter accumulator
__device__ float g_sdeg[MAXN];
__device__ float g_rdeg[MAXN];
__device__ float g_an  [DD];                  // sum over nodes of final h
__device__ float g_gvec[DD];                  // globals @ W3 + b3

// ---------------- kernel 1: zero scratch ----------------
__global__ void k_zero(int n) {
    long tid    = (long)blockIdx.x * blockDim.x + threadIdx.x;
    long stride = (long)gridDim.x * blockDim.x;
    long nd4 = (long)n * (DD / 4);
    float4 z = make_float4(0.f, 0.f, 0.f, 0.f);
    for (long i = tid; i < nd4; i += stride) ((float4*)g_agg)[i] = z;
    for (long i = tid; i < n; i += stride) { g_sdeg[i] = 0.f; g_rdeg[i] = 0.f; }
    if (tid < DD) g_an[tid] = 0.f;
}

// ---------------- kernel 2: degrees ----------------
__global__ void k_deg(const int* __restrict__ snd, const int* __restrict__ rcv, int e) {
    int i = blockIdx.x * blockDim.x + threadIdx.x;
    if (i < e) {
        atomicAdd(&g_sdeg[snd[i]], 1.0f);
        atomicAdd(&g_rdeg[rcv[i]], 1.0f);
    }
}

// ---------------- kernel 3: fused dual GEMM ----------------
// h1 = nodes @ W1 + b1            -> written into d_out (temp storage)
// conv = (nodes @ W2 + b2) * rsqrt(max(send_deg,1)) -> g_conv
// BM=64 rows/block, BK=32 k-chunk, 256 threads, per-thread tile 4 rows x 8 cols x 2 mats.
#define BM 64
#define BK 32
__global__ void __launch_bounds__(256) k_gemm(
    const float* __restrict__ nodes,
    const float* __restrict__ W1, const float* __restrict__ b1,
    const float* __restrict__ W2, const float* __restrict__ b2,
    float* __restrict__ outH, int n)
{
    __shared__ float Ws1[BK][DD];
    __shared__ float Ws2[BK][DD];
    __shared__ float As[BM][BK + 1];   // +1 pad: kills 2-way conflict on a-reads

    int tid = threadIdx.x;
    int tx = tid & 15;        // col group: 8 cols
    int ty = tid >> 4;        // row group: 4 rows
    int tx8 = tx * 8;
    int ty4 = ty * 4;
    int row0 = blockIdx.x * BM;

    float acc1[4][8];
    float acc2[4][8];
#pragma unroll
    for (int i = 0; i < 4; i++)
#pragma unroll
        for (int j = 0; j < 8; j++) { acc1[i][j] = 0.f; acc2[i][j] = 0.f; }

    for (int k0 = 0; k0 < DD; k0 += BK) {
        // load W chunks: BK*DD = 4096 floats = 1024 float4 each
        const float4* w1v = (const float4*)(W1 + k0 * DD);
        const float4* w2v = (const float4*)(W2 + k0 * DD);
        for (int j = tid; j < (BK * DD) / 4; j += 256) {
            ((float4*)Ws1)[j] = w1v[j];
            ((float4*)Ws2)[j] = w2v[j];
        }
        // load A chunk: BM rows x BK cols = 512 float4
        for (int j = tid; j < (BM * BK) / 4; j += 256) {
            int row = j >> 3;        // BK/4 = 8 float4 per row
            int kg  = j & 7;
            float4 v = make_float4(0.f, 0.f, 0.f, 0.f);
            if (row0 + row < n)
                v = ((const float4*)(nodes + (long)(row0 + row) * DD + k0))[kg];
            As[row][kg * 4 + 0] = v.x;
            As[row][kg * 4 + 1] = v.y;
            As[row][kg * 4 + 2] = v.z;
            As[row][kg * 4 + 3] = v.w;
        }
        __syncthreads();

#pragma unroll
        for (int k = 0; k < BK; k++) {
            float a0 = As[ty4 + 0][k];
            float a1 = As[ty4 + 1][k];
            float a2 = As[ty4 + 2][k];
            float a3 = As[ty4 + 3][k];
            float4 w1a = ((const float4*)Ws1[k])[tx * 2];
            float4 w1b = ((const float4*)Ws1[k])[tx * 2 + 1];
            float4 w2a = ((const float4*)Ws2[k])[tx * 2];
            float4 w2b = ((const float4*)Ws2[k])[tx * 2 + 1];
            float a[4] = {a0, a1, a2, a3};
#pragma unroll
            for (int i = 0; i < 4; i++) {
                acc1[i][0] += a[i] * w1a.x; acc1[i][1] += a[i] * w1a.y;
                acc1[i][2] += a[i] * w1a.z; acc1[i][3] += a[i] * w1a.w;
                acc1[i][4] += a[i] * w1b.x; acc1[i][5] += a[i] * w1b.y;
                acc1[i][6] += a[i] * w1b.z; acc1[i][7] += a[i] * w1b.w;
                acc2[i][0] += a[i] * w2a.x; acc2[i][1] += a[i] * w2a.y;
                acc2[i][2] += a[i] * w2a.z; acc2[i][3] += a[i] * w2a.w;
                acc2[i][4] += a[i] * w2b.x; acc2[i][5] += a[i] * w2b.y;
                acc2[i][6] += a[i] * w2b.z; acc2[i][7] += a[i] * w2b.w;
            }
        }
        __syncthreads();
    }

#pragma unroll
    for (int i = 0; i < 4; i++) {
        int row = row0 + ty4 + i;
        if (row >= n) continue;
        float f = rsqrtf(fmaxf(g_sdeg[row], 1.0f));
        long base = (long)row * DD + tx8;
#pragma unroll
        for (int j = 0; j < 8; j++) {
            int col = tx8 + j;
            outH[base + j]   = acc1[i][j] + b1[col];
            g_conv[base + j] = (acc2[i][j] + b2[col]) * f;
        }
    }
}

// ---------------- kernel 3b: gvec = globals @ W3 + b3 ----------------
__global__ void k_gvec(const float* __restrict__ g, const float* __restrict__ W3,
                       const float* __restrict__ b3) {
    int c = threadIdx.x;
    float s = b3[c];
    for (int k = 0; k < DD; k++) s += g[k] * W3[k * DD + c];
    g_gvec[c] = s;
}

// ---------------- kernel 4: edge scatter ----------------
// one warp per edge; lane handles 4 contiguous floats; vector float4 atomics (sm_90+)
__global__ void k_scatter(const int* __restrict__ snd, const int* __restrict__ rcv, int e) {
    int gw = (blockIdx.x * blockDim.x + threadIdx.x) >> 5;
    int lane = threadIdx.x & 31;
    if (gw >= e) return;
    int s = snd[gw];
    int r = rcv[gw];
    float4 v = ((const float4*)(g_conv + (long)s * DD))[lane];
    atomicAdd(((float4*)(g_agg + (long)r * DD)) + lane, v);
}

// ---------------- kernel 5: finalize h, accumulate an ----------------
#define RPB 64
__global__ void k_final(const float* __restrict__ nodes, float* __restrict__ out, int n) {
    __shared__ float red[256];
    int c    = threadIdx.x & (DD - 1);
    int half = threadIdx.x >> 7;       // 0/1: interleave rows
    int rs0  = blockIdx.x * RPB;
    int rs1  = min(rs0 + RPB, n);
    float gv = g_gvec[c];
    float local = 0.f;
    for (int r = rs0 + half; r < rs1; r += 2) {
        float rsn = rsqrtf(fmaxf(g_rdeg[r], 1.0f));
        long idx = (long)r * DD + c;
        float v = out[idx] + g_agg[idx] * rsn + gv;
        v = fmaxf(v, 0.f) + nodes[idx];
        out[idx] = v;
        local += v;
    }
    red[threadIdx.x] = local;
    __syncthreads();
    if (half == 0) atomicAdd(&g_an[c], red[c] + red[c + DD]);
}

// ---------------- kernel 6: global update ----------------
__global__ void k_gout(const float* __restrict__ g, const float* __restrict__ Wg,
                       const float* __restrict__ bg, float* __restrict__ out, long off) {
    int c = threadIdx.x;
    float s = bg[c];
    for (int k = 0; k < DD; k++)  s += g_an[k] * Wg[k * DD + c];
    for (int k = 0; k < DD; k++)  s += g[k] * Wg[(DD + k) * DD + c];
    out[off + c] = g[c] + fmaxf(s, 0.f);
}

// ---------------- launch ----------------
extern "C" void kernel_launch(void* const* d_in, const int* in_sizes, int n_in,
                              void* d_out, int out_size) {
    const float* nodes    = (const float*)d_in[0];
    const float* globals_ = (const float*)d_in[1];
    const int*   senders  = (const int*)d_in[2];
    const int*   receivers= (const int*)d_in[3];
    const float* W1w = (const float*)d_in[4];
    const float* W1b = (const float*)d_in[5];
    const float* W2w = (const float*)d_in[6];
    const float* W2b = (const float*)d_in[7];
    const float* W3w = (const float*)d_in[8];
    const float* W3b = (const float*)d_in[9];
    const float* Wgw = (const float*)d_in[10];
    const float* Wgb = (const float*)d_in[11];
    float* out = (float*)d_out;

    int n = in_sizes[0] / DD;
    int e = in_sizes[2];

    k_zero<<<1024, 256>>>(n);
    k_deg<<<(e + 255) / 256, 256>>>(senders, receivers, e);
    k_gemm<<<(n + BM - 1) / BM, 256>>>(nodes, W1w, W1b, W2w, W2b, out, n);
    k_gvec<<<1, DD>>>(globals_, W3w, W3b);
    k_scatter<<<(e + 7) / 8, 256>>>(senders, receivers, e);
    k_final<<<(n + RPB - 1) / RPB, 256>>>(nodes, out, n);
    k_gout<<<1, DD>>>(globals_, Wgw, Wgb, out, (long)n * DD);
}

// round 6
// speedup vs baseline: 1.1649x; 1.1649x over previous
#include <cuda_runtime.h>

#define DD 128
#define MAXN 100000
#define MAXE 640000

typedef unsigned long long u64;

__device__ __forceinline__ u64 pack2(float lo, float hi) {
    u64 r; asm("mov.b64 %0, {%1, %2};" : "=l"(r) : "f"(lo), "f"(hi)); return r;
}
__device__ __forceinline__ void unpack2(u64 v, float &lo, float &hi) {
    asm("mov.b64 {%0, %1}, %2;" : "=f"(lo), "=f"(hi) : "l"(v));
}
__device__ __forceinline__ void ffma2(u64 &d, u64 a, u64 b) {
    asm("fma.rn.f32x2 %0, %1, %2, %0;" : "+l"(d) : "l"(a), "l"(b));
}

// ---------------- scratch (no allocations allowed) ----------------
__device__ float g_conv[(size_t)MAXN * DD];   // W2 projection, pre-scaled by rsqrt(send_deg)
__device__ float g_agg [(size_t)MAXN * DD];   // scatter accumulator
__device__ float g_sdeg[MAXN];
__device__ float g_rdeg[MAXN];
__device__ float g_an  [DD];                  // sum over nodes of final h
__device__ float g_gvec[DD];                  // globals @ W3 + b3

// ---------------- kernel 1: zero scratch ----------------
__global__ void k_zero(int n) {
    long tid    = (long)blockIdx.x * blockDim.x + threadIdx.x;
    long stride = (long)gridDim.x * blockDim.x;
    long nd4 = (long)n * (DD / 4);
    float4 z = make_float4(0.f, 0.f, 0.f, 0.f);
    for (long i = tid; i < nd4; i += stride) ((float4*)g_agg)[i] = z;
    for (long i = tid; i < n; i += stride) { g_sdeg[i] = 0.f; g_rdeg[i] = 0.f; }
    if (tid < DD) g_an[tid] = 0.f;
}

// ---------------- kernel 2: degrees ----------------
__global__ void k_deg(const int* __restrict__ snd, const int* __restrict__ rcv, int e) {
    int i = blockIdx.x * blockDim.x + threadIdx.x;
    if (i < e) {
        atomicAdd(&g_sdeg[snd[i]], 1.0f);
        atomicAdd(&g_rdeg[rcv[i]], 1.0f);
    }
}

// ---------------- kernel 3: fused dual GEMM (f32x2 packed FMA) ----------------
// h1 = nodes @ W1 + b1            -> d_out (temp)
// conv = (nodes @ W2 + b2) * rsqrt(max(send_deg,1)) -> g_conv
#define BM 64
#define BK 32
__global__ void __launch_bounds__(256) k_gemm(
    const float* __restrict__ nodes,
    const float* __restrict__ W1, const float* __restrict__ b1,
    const float* __restrict__ W2, const float* __restrict__ b2,
    float* __restrict__ outH, int n)
{
    __shared__ float Ws1[BK][DD];
    __shared__ float Ws2[BK][DD];
    __shared__ float As[BM][BK + 1];

    int tid = threadIdx.x;
    int tx = tid & 15;        // col group: 8 cols (4 f32x2 pairs)
    int ty = tid >> 4;        // row group: 4 rows
    int tx8 = tx * 8;
    int ty4 = ty * 4;
    int row0 = blockIdx.x * BM;

    u64 acc1[4][4];
    u64 acc2[4][4];
#pragma unroll
    for (int i = 0; i < 4; i++)
#pragma unroll
        for (int j = 0; j < 4; j++) { acc1[i][j] = pack2(0.f, 0.f); acc2[i][j] = pack2(0.f, 0.f); }

    for (int k0 = 0; k0 < DD; k0 += BK) {
        const float4* w1v = (const float4*)(W1 + k0 * DD);
        const float4* w2v = (const float4*)(W2 + k0 * DD);
        for (int j = tid; j < (BK * DD) / 4; j += 256) {
            ((float4*)Ws1)[j] = w1v[j];
            ((float4*)Ws2)[j] = w2v[j];
        }
        for (int j = tid; j < (BM * BK) / 4; j += 256) {
            int row = j >> 3;
            int kg  = j & 7;
            float4 v = make_float4(0.f, 0.f, 0.f, 0.f);
            if (row0 + row < n)
                v = ((const float4*)(nodes + (long)(row0 + row) * DD + k0))[kg];
            As[row][kg * 4 + 0] = v.x;
            As[row][kg * 4 + 1] = v.y;
            As[row][kg * 4 + 2] = v.z;
            As[row][kg * 4 + 3] = v.w;
        }
        __syncthreads();

#pragma unroll
        for (int k = 0; k < BK; k++) {
            u64 ap[4];
#pragma unroll
            for (int i = 0; i < 4; i++) {
                float a = As[ty4 + i][k];
                ap[i] = pack2(a, a);
            }
            const u64* w1p = (const u64*)&Ws1[k][tx8];   // 4 u64 = 8 floats, 32B aligned
            const u64* w2p = (const u64*)&Ws2[k][tx8];
            u64 w1r[4] = { w1p[0], w1p[1], w1p[2], w1p[3] };
            u64 w2r[4] = { w2p[0], w2p[1], w2p[2], w2p[3] };
#pragma unroll
            for (int i = 0; i < 4; i++) {
#pragma unroll
                for (int j = 0; j < 4; j++) {
                    ffma2(acc1[i][j], ap[i], w1r[j]);
                    ffma2(acc2[i][j], ap[i], w2r[j]);
                }
            }
        }
        __syncthreads();
    }

#pragma unroll
    for (int i = 0; i < 4; i++) {
        int row = row0 + ty4 + i;
        if (row >= n) continue;
        float f = rsqrtf(fmaxf(g_sdeg[row], 1.0f));
        long base = (long)row * DD + tx8;
#pragma unroll
        for (int j = 0; j < 4; j++) {
            float v1lo, v1hi, v2lo, v2hi;
            unpack2(acc1[i][j], v1lo, v1hi);
            unpack2(acc2[i][j], v2lo, v2hi);
            int col = tx8 + j * 2;
            outH[base + j*2 + 0]   = v1lo + b1[col + 0];
            outH[base + j*2 + 1]   = v1hi + b1[col + 1];
            g_conv[base + j*2 + 0] = (v2lo + b2[col + 0]) * f;
            g_conv[base + j*2 + 1] = (v2hi + b2[col + 1]) * f;
        }
    }
}

// ---------------- kernel 3b: gvec = globals @ W3 + b3 (parallel k-split) ----------------
__global__ void k_gvec(const float* __restrict__ g, const float* __restrict__ W3,
                       const float* __restrict__ b3) {
    __shared__ float part[4][DD];
    int c = threadIdx.x & (DD - 1);
    int p = threadIdx.x >> 7;           // 512 threads: 4 k-partitions
    float s = 0.f;
    int kbeg = p * 32;
#pragma unroll
    for (int k = 0; k < 32; k += 4) {
        float s0 = g[kbeg + k + 0] * W3[(kbeg + k + 0) * DD + c];
        float s1 = g[kbeg + k + 1] * W3[(kbeg + k + 1) * DD + c];
        float s2 = g[kbeg + k + 2] * W3[(kbeg + k + 2) * DD + c];
        float s3 = g[kbeg + k + 3] * W3[(kbeg + k + 3) * DD + c];
        s += (s0 + s1) + (s2 + s3);
    }
    part[p][c] = s;
    __syncthreads();
    if (p == 0)
        g_gvec[c] = part[0][c] + part[1][c] + part[2][c] + part[3][c] + b3[c];
}

// ---------------- kernel 4: edge scatter ----------------
__global__ void k_scatter(const int* __restrict__ snd, const int* __restrict__ rcv, int e) {
    int gw = (blockIdx.x * blockDim.x + threadIdx.x) >> 5;
    int lane = threadIdx.x & 31;
    if (gw >= e) return;
    int s = snd[gw];
    int r = rcv[gw];
    float4 v = ((const float4*)(g_conv + (long)s * DD))[lane];
    atomicAdd(((float4*)(g_agg + (long)r * DD)) + lane, v);
}

// ---------------- kernel 5: finalize h, accumulate an ----------------
#define RPB 64
__global__ void k_final(const float* __restrict__ nodes, float* __restrict__ out, int n) {
    __shared__ float red[256];
    int c    = threadIdx.x & (DD - 1);
    int half = threadIdx.x >> 7;
    int rs0  = blockIdx.x * RPB;
    int rs1  = min(rs0 + RPB, n);
    float gv = g_gvec[c];
    float local = 0.f;
    for (int r = rs0 + half; r < rs1; r += 2) {
        float rsn = rsqrtf(fmaxf(g_rdeg[r], 1.0f));
        long idx = (long)r * DD + c;
        float v = out[idx] + g_agg[idx] * rsn + gv;
        v = fmaxf(v, 0.f) + nodes[idx];
        out[idx] = v;
        local += v;
    }
    red[threadIdx.x] = local;
    __syncthreads();
    if (half == 0) atomicAdd(&g_an[c], red[c] + red[c + DD]);
}

// ---------------- kernel 6: global update (parallel k-split) ----------------
__global__ void k_gout(const float* __restrict__ g, const float* __restrict__ Wg,
                       const float* __restrict__ bg, float* __restrict__ out, long off) {
    __shared__ float part[4][DD];
    int c = threadIdx.x & (DD - 1);
    int p = threadIdx.x >> 7;           // 512 threads: 4 partitions over 256 ks
    float s = 0.f;
    int kbeg = p * 64;
#pragma unroll
    for (int k = 0; k < 64; k += 4) {
        int kk = kbeg + k;
        float x0 = (kk + 0 < DD) ? g_an[kk + 0] : g[kk + 0 - DD];
        float x1 = (kk + 1 < DD) ? g_an[kk + 1] : g[kk + 1 - DD];
        float x2 = (kk + 2 < DD) ? g_an[kk + 2] : g[kk + 2 - DD];
        float x3 = (kk + 3 < DD) ? g_an[kk + 3] : g[kk + 3 - DD];
        float s0 = x0 * Wg[(kk + 0) * DD + c];
        float s1 = x1 * Wg[(kk + 1) * DD + c];
        float s2 = x2 * Wg[(kk + 2) * DD + c];
        float s3 = x3 * Wg[(kk + 3) * DD + c];
        s += (s0 + s1) + (s2 + s3);
    }
    part[p][c] = s;
    __syncthreads();
    if (p == 0) {
        float v = part[0][c] + part[1][c] + part[2][c] + part[3][c] + bg[c];
        out[off + c] = g[c] + fmaxf(v, 0.f);
    }
}

// ---------------- launch ----------------
extern "C" void kernel_launch(void* const* d_in, const int* in_sizes, int n_in,
                              void* d_out, int out_size) {
    const float* nodes    = (const float*)d_in[0];
    const float* globals_ = (const float*)d_in[1];
    const int*   senders  = (const int*)d_in[2];
    const int*   receivers= (const int*)d_in[3];
    const float* W1w = (const float*)d_in[4];
    const float* W1b = (const float*)d_in[5];
    const float* W2w = (const float*)d_in[6];
    const float* W2b = (const float*)d_in[7];
    const float* W3w = (const float*)d_in[8];
    const float* W3b = (const float*)d_in[9];
    const float* Wgw = (const float*)d_in[10];
    const float* Wgb = (const float*)d_in[11];
    float* out = (float*)d_out;

    int n = in_sizes[0] / DD;
    int e = in_sizes[2];

    k_zero<<<1024, 256>>>(n);
    k_deg<<<(e + 255) / 256, 256>>>(senders, receivers, e);
    k_gemm<<<(n + BM - 1) / BM, 256>>>(nodes, W1w, W1b, W2w, W2b, out, n);
    k_gvec<<<1, 512>>>(globals_, W3w, W3b);
    k_scatter<<<(e + 7) / 8, 256>>>(senders, receivers, e);
    k_final<<<(n + RPB - 1) / RPB, 256>>>(nodes, out, n);
    k_gout<<<1, 512>>>(globals_, Wgw, Wgb, out, (long)n * DD);
}

// round 14
// speedup vs baseline: 1.7750x; 1.5238x over previous
#include <cuda_runtime.h>
#include <cuda_bf16.h>
#include <cstdint>

#define DD 128
#define MAXN 100000
#define MAXE 640000

// ---------------- scratch (no allocations allowed) ----------------
__device__ float g_conv[(size_t)MAXN * DD];
__device__ float g_agg [(size_t)MAXN * DD];
__device__ float g_sdeg[MAXN];
__device__ float g_rdeg[MAXN];
__device__ float g_an  [DD];
__device__ float g_gvec[DD];
// W terms in [n][k] layout with pitch 136 (smem image): W1h, W1l, W2h, W2l
#define WPITCH 136
#define WTERM  (128 * WPITCH)          // 17408 elems = 34816 B
__device__ __nv_bfloat16 g_wstage[4 * WTERM];

// ---------------- PTX helpers ----------------
__device__ __forceinline__ uint32_t smem_u32(const void* p) {
    uint32_t a;
    asm("{ .reg .u64 t; cvta.to.shared.u64 t, %1; cvt.u32.u64 %0, t; }" : "=r"(a) : "l"(p));
    return a;
}
__device__ __forceinline__ void ldsm4(uint32_t* r, uint32_t addr) {
    asm volatile("ldmatrix.sync.aligned.m8n8.x4.shared.b16 {%0,%1,%2,%3}, [%4];"
                 : "=r"(r[0]), "=r"(r[1]), "=r"(r[2]), "=r"(r[3]) : "r"(addr));
}
__device__ __forceinline__ void mma16816(float* c, const uint32_t* a, uint32_t b0, uint32_t b1) {
    asm volatile("mma.sync.aligned.m16n8k16.row.col.f32.bf16.bf16.f32 "
                 "{%0,%1,%2,%3}, {%4,%5,%6,%7}, {%8,%9}, {%0,%1,%2,%3};"
                 : "+f"(c[0]), "+f"(c[1]), "+f"(c[2]), "+f"(c[3])
                 : "r"(a[0]), "r"(a[1]), "r"(a[2]), "r"(a[3]), "r"(b0), "r"(b1));
}

// ---------------- kernel 1: zero scratch ----------------
__global__ void k_zero(int n) {
    long tid = (long)blockIdx.x * blockDim.x + threadIdx.x;
    long stride = (long)gridDim.x * blockDim.x;
    long nd4 = (long)n * (DD / 4);
    float4 z = make_float4(0.f, 0.f, 0.f, 0.f);
    for (long i = tid; i < nd4; i += stride) ((float4*)g_agg)[i] = z;
    for (long i = tid; i < n; i += stride) { g_sdeg[i] = 0.f; g_rdeg[i] = 0.f; }
    if (tid < DD) g_an[tid] = 0.f;
}

// ---------------- kernel 2: degrees ----------------
__global__ void k_deg(const int* __restrict__ snd, const int* __restrict__ rcv, int e) {
    int i = blockIdx.x * blockDim.x + threadIdx.x;
    if (i < e) {
        atomicAdd(&g_sdeg[snd[i]], 1.0f);
        atomicAdd(&g_rdeg[rcv[i]], 1.0f);
    }
}

// ---------------- kernel 2b: W -> bf16 hi/lo, [n][k] pitch-136 ----------------
__global__ void k_wconv(const float* __restrict__ W1, const float* __restrict__ W2) {
    int idx = blockIdx.x * blockDim.x + threadIdx.x;   // 65536 threads: mat(2) x n(128) x k(128)
    int mat = idx >> 14;
    int nn  = (idx >> 7) & 127;
    int k   = idx & 127;
    float w = (mat ? W2 : W1)[k * DD + nn];
    __nv_bfloat16 hi = __float2bfloat16(w);
    __nv_bfloat16 lo = __float2bfloat16(w - __bfloat162float(hi));
    int off = nn * WPITCH + k;
    g_wstage[(mat * 2 + 0) * WTERM + off] = hi;
    g_wstage[(mat * 2 + 1) * WTERM + off] = lo;
}

// ---------------- kernel 3: split-bf16 dual GEMM via mma.sync (persistent) ----------------
// smem layout (bytes): b1[512] | b2[512] | Ahi[34816] | Alo[34816] | W[4*34816]
#define SM_B1   0
#define SM_B2   512
#define SM_AHI  1024
#define SM_ALO  (SM_AHI + 34816)
#define SM_W    (SM_ALO + 34816)
#define SM_TOT  (SM_W + 4 * 34816)     // 209920 B

__global__ void __launch_bounds__(256, 1) k_mm(
    const float* __restrict__ nodes,
    const float* __restrict__ b1, const float* __restrict__ b2,
    float* __restrict__ outH, int n)
{
    extern __shared__ char smem[];
    uint32_t sb = smem_u32(smem);
    int tid = threadIdx.x;
    int warp = tid >> 5, lane = tid & 31;
    int ntiles = (n + 127) >> 7;

    // stage W terms + biases once
    {
        const float4* src = (const float4*)g_wstage;       // 139264 B = 8704 float4
        float4* dst = (float4*)(smem + SM_W);
        for (int i = tid; i < 8704; i += 256) dst[i] = src[i];
        if (tid < 32) {
            ((float4*)(smem + SM_B1))[tid] = ((const float4*)b1)[tid];
            ((float4*)(smem + SM_B2))[tid] = ((const float4*)b2)[tid];
        }
    }
    __syncthreads();

    const float* b1s = (const float*)(smem + SM_B1);
    const float* b2s = (const float*)(smem + SM_B2);

    // lane-derived ldmatrix address pieces
    uint32_t lrow = lane & 15;
    uint32_t khb  = (lane >> 4) << 4;            // 0 or 16 bytes (k half)
    uint32_t aoff = lrow * 272 + khb;            // within A tile
    uint32_t boff = ((uint32_t)warp * 16 + lrow) * 272 + khb;  // warp's n range in W tiles

    for (int tile = blockIdx.x; tile < ntiles; tile += gridDim.x) {
        int row0 = tile << 7;

        // ---- load A tile fp32, split to bf16 hi/lo, store pitch-136 ----
        for (int i = tid; i < 4096; i += 256) {
            int row = i >> 5, f4 = i & 31;
            float4 v = make_float4(0.f, 0.f, 0.f, 0.f);
            if (row0 + row < n)
                v = ((const float4*)(nodes + (long)(row0 + row) * DD))[f4];
            __nv_bfloat16 hx = __float2bfloat16(v.x), hy = __float2bfloat16(v.y);
            __nv_bfloat16 hz = __float2bfloat16(v.z), hw = __float2bfloat16(v.w);
            __nv_bfloat16 lx = __float2bfloat16(v.x - __bfloat162float(hx));
            __nv_bfloat16 ly = __float2bfloat16(v.y - __bfloat162float(hy));
            __nv_bfloat16 lz = __float2bfloat16(v.z - __bfloat162float(hz));
            __nv_bfloat16 lw = __float2bfloat16(v.w - __bfloat162float(hw));
            uint32_t off = (uint32_t)row * 272 + (uint32_t)(f4 << 3);
            uint2 hp, lp;
            hp.x = ((uint32_t)__bfloat16_as_ushort(hy) << 16) | __bfloat16_as_ushort(hx);
            hp.y = ((uint32_t)__bfloat16_as_ushort(hw) << 16) | __bfloat16_as_ushort(hz);
            lp.x = ((uint32_t)__bfloat16_as_ushort(ly) << 16) | __bfloat16_as_ushort(lx);
            lp.y = ((uint32_t)__bfloat16_as_ushort(lw) << 16) | __bfloat16_as_ushort(lz);
            *(uint2*)(smem + SM_AHI + off) = hp;
            *(uint2*)(smem + SM_ALO + off) = lp;
        }
        __syncthreads();

        // ---- compute: acc[mtile][ntile][mat][4] ----
        float acc[8][2][2][4];
#pragma unroll
        for (int m = 0; m < 8; m++)
#pragma unroll
            for (int nt = 0; nt < 2; nt++)
#pragma unroll
                for (int mt = 0; mt < 2; mt++)
#pragma unroll
                    for (int c = 0; c < 4; c++) acc[m][nt][mt][c] = 0.f;

#pragma unroll
        for (int ks = 0; ks < 8; ks++) {
            uint32_t kb = (uint32_t)ks * 32;     // k0*2 bytes
            uint32_t bf[4][4];
#pragma unroll
            for (int t = 0; t < 4; t++)
                ldsm4(bf[t], sb + SM_W + (uint32_t)t * 34816 + boff + kb);
#pragma unroll
            for (int m = 0; m < 8; m++) {
                uint32_t ah[4], al[4];
                uint32_t abase = aoff + (uint32_t)m * 4352 + kb;  // 16*272 = 4352
                ldsm4(ah, sb + SM_AHI + abase);
                ldsm4(al, sb + SM_ALO + abase);
                // W1: hi*hi + hi*lo + lo*hi
                mma16816(acc[m][0][0], ah, bf[0][0], bf[0][2]);
                mma16816(acc[m][1][0], ah, bf[0][1], bf[0][3]);
                mma16816(acc[m][0][0], ah, bf[1][0], bf[1][2]);
                mma16816(acc[m][1][0], ah, bf[1][1], bf[1][3]);
                mma16816(acc[m][0][0], al, bf[0][0], bf[0][2]);
                mma16816(acc[m][1][0], al, bf[0][1], bf[0][3]);
                // W2
                mma16816(acc[m][0][1], ah, bf[2][0], bf[2][2]);
                mma16816(acc[m][1][1], ah, bf[2][1], bf[2][3]);
                mma16816(acc[m][0][1], ah, bf[3][0], bf[3][2]);
                mma16816(acc[m][1][1], ah, bf[3][1], bf[3][3]);
                mma16816(acc[m][0][1], al, bf[2][0], bf[2][2]);
                mma16816(acc[m][1][1], al, bf[2][1], bf[2][3]);
            }
        }
        __syncthreads();   // A smem free for next tile

        // ---- epilogue ----
        int qrow = lane >> 2;            // 0..7
        int qcol = (lane & 3) << 1;      // 0,2,4,6
#pragma unroll
        for (int m = 0; m < 8; m++) {
#pragma unroll
            for (int h = 0; h < 2; h++) {
                int grow = row0 + m * 16 + qrow + h * 8;
                if (grow >= n) continue;
                float f = rsqrtf(fmaxf(g_sdeg[grow], 1.0f));
                long gb = (long)grow * DD;
#pragma unroll
                for (int nt = 0; nt < 2; nt++) {
                    int col = warp * 16 + nt * 8 + qcol;
                    float2 o1, o2;
                    o1.x = acc[m][nt][0][2 * h + 0] + b1s[col + 0];
                    o1.y = acc[m][nt][0][2 * h + 1] + b1s[col + 1];
                    o2.x = (acc[m][nt][1][2 * h + 0] + b2s[col + 0]) * f;
                    o2.y = (acc[m][nt][1][2 * h + 1] + b2s[col + 1]) * f;
                    *(float2*)(outH + gb + col)   = o1;
                    *(float2*)(g_conv + gb + col) = o2;
                }
            }
        }
    }
}

// ---------------- kernel 3b: gvec = globals @ W3 + b3 ----------------
__global__ void k_gvec(const float* __restrict__ g, const float* __restrict__ W3,
                       const float* __restrict__ b3) {
    __shared__ float part[4][DD];
    int c = threadIdx.x & (DD - 1);
    int p = threadIdx.x >> 7;
    float s = 0.f;
    int kbeg = p * 32;
#pragma unroll
    for (int k = 0; k < 32; k += 4) {
        float s0 = g[kbeg + k + 0] * W3[(kbeg + k + 0) * DD + c];
        float s1 = g[kbeg + k + 1] * W3[(kbeg + k + 1) * DD + c];
        float s2 = g[kbeg + k + 2] * W3[(kbeg + k + 2) * DD + c];
        float s3 = g[kbeg + k + 3] * W3[(kbeg + k + 3) * DD + c];
        s += (s0 + s1) + (s2 + s3);
    }
    part[p][c] = s;
    __syncthreads();
    if (p == 0)
        g_gvec[c] = part[0][c] + part[1][c] + part[2][c] + part[3][c] + b3[c];
}

// ---------------- kernel 4: edge scatter ----------------
__global__ void k_scatter(const int* __restrict__ snd, const int* __restrict__ rcv, int e) {
    int gw = (blockIdx.x * blockDim.x + threadIdx.x) >> 5;
    int lane = threadIdx.x & 31;
    if (gw >= e) return;
    int s = snd[gw];
    int r = rcv[gw];
    float4 v = ((const float4*)(g_conv + (long)s * DD))[lane];
    atomicAdd(((float4*)(g_agg + (long)r * DD)) + lane, v);
}

// ---------------- kernel 5: finalize h, accumulate an ----------------
#define RPB 64
__global__ void k_final(const float* __restrict__ nodes, float* __restrict__ out, int n) {
    __shared__ float red[256];
    int c    = threadIdx.x & (DD - 1);
    int half = threadIdx.x >> 7;
    int rs0  = blockIdx.x * RPB;
    int rs1  = min(rs0 + RPB, n);
    float gv = g_gvec[c];
    float local = 0.f;
    for (int r = rs0 + half; r < rs1; r += 2) {
        float rsn = rsqrtf(fmaxf(g_rdeg[r], 1.0f));
        long idx = (long)r * DD + c;
        float v = out[idx] + g_agg[idx] * rsn + gv;
        v = fmaxf(v, 0.f) + nodes[idx];
        out[idx] = v;
        local += v;
    }
    red[threadIdx.x] = local;
    __syncthreads();
    if (half == 0) atomicAdd(&g_an[c], red[c] + red[c + DD]);
}

// ---------------- kernel 6: global update ----------------
__global__ void k_gout(const float* __restrict__ g, const float* __restrict__ Wg,
                       const float* __restrict__ bg, float* __restrict__ out, long off) {
    __shared__ float part[4][DD];
    int c = threadIdx.x & (DD - 1);
    int p = threadIdx.x >> 7;
    float s = 0.f;
    int kbeg = p * 64;
#pragma unroll
    for (int k = 0; k < 64; k += 4) {
        int kk = kbeg + k;
        float x0 = (kk + 0 < DD) ? g_an[kk + 0] : g[kk + 0 - DD];
        float x1 = (kk + 1 < DD) ? g_an[kk + 1] : g[kk + 1 - DD];
        float x2 = (kk + 2 < DD) ? g_an[kk + 2] : g[kk + 2 - DD];
        float x3 = (kk + 3 < DD) ? g_an[kk + 3] : g[kk + 3 - DD];
        s += (x0 * Wg[(kk + 0) * DD + c] + x1 * Wg[(kk + 1) * DD + c])
           + (x2 * Wg[(kk + 2) * DD + c] + x3 * Wg[(kk + 3) * DD + c]);
    }
    part[p][c] = s;
    __syncthreads();
    if (p == 0) {
        float v = part[0][c] + part[1][c] + part[2][c] + part[3][c] + bg[c];
        out[off + c] = g[c] + fmaxf(v, 0.f);
    }
}

// ---------------- launch ----------------
extern "C" void kernel_launch(void* const* d_in, const int* in_sizes, int n_in,
                              void* d_out, int out_size) {
    const float* nodes    = (const float*)d_in[0];
    const float* globals_ = (const float*)d_in[1];
    const int*   senders  = (const int*)d_in[2];
    const int*   receivers= (const int*)d_in[3];
    const float* W1w = (const float*)d_in[4];
    const float* W1b = (const float*)d_in[5];
    const float* W2w = (const float*)d_in[6];
    const float* W2b = (const float*)d_in[7];
    const float* W3w = (const float*)d_in[8];
    const float* W3b = (const float*)d_in[9];
    const float* Wgw = (const float*)d_in[10];
    const float* Wgb = (const float*)d_in[11];
    float* out = (float*)d_out;

    int n = in_sizes[0] / DD;
    int e = in_sizes[2];

    cudaFuncSetAttribute(k_mm, cudaFuncAttributeMaxDynamicSharedMemorySize, SM_TOT);

    k_zero<<<1024, 256>>>(n);
    k_deg<<<(e + 255) / 256, 256>>>(senders, receivers, e);
    k_wconv<<<256, 256>>>(W1w, W2w);
    k_mm<<<148, 256, SM_TOT>>>(nodes, W1b, W2b, out, n);
    k_gvec<<<1, 512>>>(globals_, W3w, W3b);
    k_scatter<<<(e + 7) / 8, 256>>>(senders, receivers, e);
    k_final<<<(n + RPB - 1) / RPB, 256>>>(nodes, out, n);
    k_gout<<<1, 512>>>(globals_, Wgw, Wgb, out, (long)n * DD);
}

// round 15
// speedup vs baseline: 1.9007x; 1.0708x over previous
#include <cuda_runtime.h>
#include <cuda_bf16.h>
#include <cstdint>

#define DD 128
#define MAXN 100000
#define MAXN_PAD 100032      // 1563 * 64
#define MAXE 640000

// ---------------- scratch (no allocations allowed) ----------------
__device__ float g_conv[(size_t)MAXN * DD];
__device__ float g_agg [(size_t)MAXN * DD];
__device__ float g_sdeg[MAXN];
__device__ float g_rdeg[MAXN];
__device__ float g_an  [DD];
__device__ float g_gvec[DD];
// W terms in [n][k] layout with pitch 136 elems (272 B): W1h, W1l, W2h, W2l
#define WPITCH 136
#define WTERM  (128 * WPITCH)          // 17408 elems = 34816 B
__device__ __nv_bfloat16 g_wstage[4 * WTERM];
// pre-converted A (bf16 hi/lo), contiguous [MAXN_PAD][128]
__device__ __nv_bfloat16 g_ahi[(size_t)MAXN_PAD * DD];
__device__ __nv_bfloat16 g_alo[(size_t)MAXN_PAD * DD];

// ---------------- PTX helpers ----------------
__device__ __forceinline__ uint32_t smem_u32(const void* p) {
    uint32_t a;
    asm("{ .reg .u64 t; cvta.to.shared.u64 t, %1; cvt.u32.u64 %0, t; }" : "=r"(a) : "l"(p));
    return a;
}
__device__ __forceinline__ void ldsm4(uint32_t* r, uint32_t addr) {
    asm volatile("ldmatrix.sync.aligned.m8n8.x4.shared.b16 {%0,%1,%2,%3}, [%4];"
                 : "=r"(r[0]), "=r"(r[1]), "=r"(r[2]), "=r"(r[3]) : "r"(addr));
}
__device__ __forceinline__ void mma16816(float* c, const uint32_t* a, uint32_t b0, uint32_t b1) {
    asm volatile("mma.sync.aligned.m16n8k16.row.col.f32.bf16.bf16.f32 "
                 "{%0,%1,%2,%3}, {%4,%5,%6,%7}, {%8,%9}, {%0,%1,%2,%3};"
                 : "+f"(c[0]), "+f"(c[1]), "+f"(c[2]), "+f"(c[3])
                 : "r"(a[0]), "r"(a[1]), "r"(a[2]), "r"(a[3]), "r"(b0), "r"(b1));
}
__device__ __forceinline__ void cp16(uint32_t dst, const void* src) {
    asm volatile("cp.async.cg.shared.global [%0], [%1], 16;" :: "r"(dst), "l"(src));
}
#define CP_COMMIT() asm volatile("cp.async.commit_group;" ::: "memory")
#define CP_WAIT1()  asm volatile("cp.async.wait_group 1;" ::: "memory")

// ---------------- kernel 1: zero scratch ----------------
__global__ void k_zero(int n) {
    long tid = (long)blockIdx.x * blockDim.x + threadIdx.x;
    long stride = (long)gridDim.x * blockDim.x;
    long nd4 = (long)n * (DD / 4);
    float4 z = make_float4(0.f, 0.f, 0.f, 0.f);
    for (long i = tid; i < nd4; i += stride) ((float4*)g_agg)[i] = z;
    for (long i = tid; i < n; i += stride) { g_sdeg[i] = 0.f; g_rdeg[i] = 0.f; }
    if (tid < DD) g_an[tid] = 0.f;
}

// ---------------- kernel 2: degrees ----------------
__global__ void k_deg(const int* __restrict__ snd, const int* __restrict__ rcv, int e) {
    int i = blockIdx.x * blockDim.x + threadIdx.x;
    if (i < e) {
        atomicAdd(&g_sdeg[snd[i]], 1.0f);
        atomicAdd(&g_rdeg[rcv[i]], 1.0f);
    }
}

// ---------------- kernel 2b: W -> bf16 hi/lo, [n][k] pitch-136 ----------------
__global__ void k_wconv(const float* __restrict__ W1, const float* __restrict__ W2) {
    int idx = blockIdx.x * blockDim.x + threadIdx.x;
    int mat = idx >> 14;
    int nn  = (idx >> 7) & 127;
    int k   = idx & 127;
    float w = (mat ? W2 : W1)[k * DD + nn];
    __nv_bfloat16 hi = __float2bfloat16(w);
    __nv_bfloat16 lo = __float2bfloat16(w - __bfloat162float(hi));
    int off = nn * WPITCH + k;
    g_wstage[(mat * 2 + 0) * WTERM + off] = hi;
    g_wstage[(mat * 2 + 1) * WTERM + off] = lo;
}

// ---------------- kernel 2c: A -> bf16 hi/lo (padded, contiguous) ----------------
__global__ void k_aconv(const float* __restrict__ nodes, int n) {
    long i4 = (long)blockIdx.x * blockDim.x + threadIdx.x;   // one float4 per thread
    long tot = (long)MAXN_PAD * DD / 4;
    long stride = (long)gridDim.x * blockDim.x;
    for (; i4 < tot; i4 += stride) {
        long row = i4 >> 5;
        float4 v = make_float4(0.f, 0.f, 0.f, 0.f);
        if (row < n) v = ((const float4*)nodes)[i4];
        __nv_bfloat16 hx = __float2bfloat16(v.x), hy = __float2bfloat16(v.y);
        __nv_bfloat16 hz = __float2bfloat16(v.z), hw = __float2bfloat16(v.w);
        __nv_bfloat16 lx = __float2bfloat16(v.x - __bfloat162float(hx));
        __nv_bfloat16 ly = __float2bfloat16(v.y - __bfloat162float(hy));
        __nv_bfloat16 lz = __float2bfloat16(v.z - __bfloat162float(hz));
        __nv_bfloat16 lw = __float2bfloat16(v.w - __bfloat162float(hw));
        uint2 hp, lp;
        hp.x = ((uint32_t)__bfloat16_as_ushort(hy) << 16) | __bfloat16_as_ushort(hx);
        hp.y = ((uint32_t)__bfloat16_as_ushort(hw) << 16) | __bfloat16_as_ushort(hz);
        lp.x = ((uint32_t)__bfloat16_as_ushort(ly) << 16) | __bfloat16_as_ushort(lx);
        lp.y = ((uint32_t)__bfloat16_as_ushort(lw) << 16) | __bfloat16_as_ushort(lz);
        ((uint2*)g_ahi)[i4] = hp;
        ((uint2*)g_alo)[i4] = lp;
    }
}

// ---------------- kernel 3: split-bf16 dual GEMM, 512 thr, cp.async double-buffer ----
// smem: b1[512] | b2[512] | A: 2 buffers x (Ahi 17408 + Alo 17408) | W[4*34816]
#define SM_B1   0
#define SM_B2   512
#define SM_A    1024
#define ABUF    34816                  // one buffer: Ahi + Alo (64 rows x 272 B each)
#define SM_W    (SM_A + 2 * ABUF)      // 70656
#define SM_TOT  (SM_W + 4 * 34816)    // 209920 B

__device__ __forceinline__ void load_tile_a(uint32_t sb, int tile, int buf, int tid) {
    uint32_t base = sb + SM_A + (uint32_t)buf * ABUF;
    long row0 = (long)tile * 64;
#pragma unroll
    for (int j = 0; j < 4; j++) {
        int c = tid + j * 512;                 // 2048 chunks of 16 B
        int term = c >> 10;
        int rr   = (c >> 4) & 63;
        int col  = c & 15;
        uint32_t dst = base + (uint32_t)term * 17408 + (uint32_t)rr * 272 + (uint32_t)(col << 4);
        const char* srcb = (const char*)(term ? g_alo : g_ahi)
                         + ((row0 + rr) << 8) + (col << 4);
        cp16(dst, srcb);
    }
}

__global__ void __launch_bounds__(512, 1) k_mm(
    const float* __restrict__ b1, const float* __restrict__ b2,
    float* __restrict__ outH, int n)
{
    extern __shared__ char smem[];
    uint32_t sb = smem_u32(smem);
    int tid = threadIdx.x;
    int warp = tid >> 5, lane = tid & 31;
    int wn = warp & 7;                  // n-range: 16 cols each
    int wm = warp >> 3;                 // m-half: rows 0-31 / 32-63
    int ntiles = (n + 63) >> 6;

    // stage W terms + biases once
    {
        const float4* src = (const float4*)g_wstage;     // 8704 float4
        float4* dst = (float4*)(smem + SM_W);
        for (int i = tid; i < 8704; i += 512) dst[i] = src[i];
        if (tid < 32) {
            ((float4*)(smem + SM_B1))[tid] = ((const float4*)b1)[tid];
            ((float4*)(smem + SM_B2))[tid] = ((const float4*)b2)[tid];
        }
    }

    const float* b1s = (const float*)(smem + SM_B1);
    const float* b2s = (const float*)(smem + SM_B2);

    uint32_t lrow = lane & 15;
    uint32_t khb  = (lane >> 4) << 4;
    uint32_t aoff = lrow * 272 + khb + (uint32_t)wm * (32 * 272);
    uint32_t boff = ((uint32_t)wn * 16 + lrow) * 272 + khb;

    int qrow = lane >> 2;
    int qcol = (lane & 3) << 1;

    // prologue: first tile into buffer 0
    int tile = blockIdx.x;
    if (tile < ntiles) load_tile_a(sb, tile, 0, tid);
    CP_COMMIT();
    int bufc = 0;
    __syncthreads();   // W staging also complete after this

    for (; tile < ntiles; tile += gridDim.x) {
        int nexttile = tile + gridDim.x;
        if (nexttile < ntiles) load_tile_a(sb, nexttile, bufc ^ 1, tid);
        CP_COMMIT();
        CP_WAIT1();            // current tile's loads complete
        __syncthreads();

        uint32_t abase = sb + SM_A + (uint32_t)bufc * ABUF + aoff;

        float acc[2][2][2][4];
#pragma unroll
        for (int m = 0; m < 2; m++)
#pragma unroll
            for (int nt = 0; nt < 2; nt++)
#pragma unroll
                for (int mt = 0; mt < 2; mt++)
#pragma unroll
                    for (int c = 0; c < 4; c++) acc[m][nt][mt][c] = 0.f;

#pragma unroll
        for (int ks = 0; ks < 8; ks++) {
            uint32_t kb = (uint32_t)ks * 32;
            uint32_t bf[4][4];
#pragma unroll
            for (int t = 0; t < 4; t++)
                ldsm4(bf[t], sb + SM_W + (uint32_t)t * 34816 + boff + kb);
#pragma unroll
            for (int m = 0; m < 2; m++) {
                uint32_t ah[4], al[4];
                uint32_t ab = abase + (uint32_t)m * (16 * 272) + kb;
                ldsm4(ah, ab);
                ldsm4(al, ab + 17408);
                // W1: hi*hi + hi*lo + lo*hi
                mma16816(acc[m][0][0], ah, bf[0][0], bf[0][2]);
                mma16816(acc[m][1][0], ah, bf[0][1], bf[0][3]);
                mma16816(acc[m][0][0], ah, bf[1][0], bf[1][2]);
                mma16816(acc[m][1][0], ah, bf[1][1], bf[1][3]);
                mma16816(acc[m][0][0], al, bf[0][0], bf[0][2]);
                mma16816(acc[m][1][0], al, bf[0][1], bf[0][3]);
                // W2
                mma16816(acc[m][0][1], ah, bf[2][0], bf[2][2]);
                mma16816(acc[m][1][1], ah, bf[2][1], bf[2][3]);
                mma16816(acc[m][0][1], ah, bf[3][0], bf[3][2]);
                mma16816(acc[m][1][1], ah, bf[3][1], bf[3][3]);
                mma16816(acc[m][0][1], al, bf[2][0], bf[2][2]);
                mma16816(acc[m][1][1], al, bf[2][1], bf[2][3]);
            }
        }
        __syncthreads();   // all reads of this buffer done before it is refilled

        int row0 = tile << 6;
#pragma unroll
        for (int m = 0; m < 2; m++) {
#pragma unroll
            for (int h = 0; h < 2; h++) {
                int grow = row0 + wm * 32 + m * 16 + qrow + h * 8;
                if (grow >= n) continue;
                float f = rsqrtf(fmaxf(g_sdeg[grow], 1.0f));
                long gb = (long)grow * DD;
#pragma unroll
                for (int nt = 0; nt < 2; nt++) {
                    int col = wn * 16 + nt * 8 + qcol;
                    float2 o1, o2;
                    o1.x = acc[m][nt][0][2 * h + 0] + b1s[col + 0];
                    o1.y = acc[m][nt][0][2 * h + 1] + b1s[col + 1];
                    o2.x = (acc[m][nt][1][2 * h + 0] + b2s[col + 0]) * f;
                    o2.y = (acc[m][nt][1][2 * h + 1] + b2s[col + 1]) * f;
                    *(float2*)(outH + gb + col)   = o1;
                    *(float2*)(g_conv + gb + col) = o2;
                }
            }
        }
        bufc ^= 1;
    }
}

// ---------------- kernel 3b: gvec = globals @ W3 + b3 ----------------
__global__ void k_gvec(const float* __restrict__ g, const float* __restrict__ W3,
                       const float* __restrict__ b3) {
    __shared__ float part[4][DD];
    int c = threadIdx.x & (DD - 1);
    int p = threadIdx.x >> 7;
    float s = 0.f;
    int kbeg = p * 32;
#pragma unroll
    for (int k = 0; k < 32; k += 4) {
        float s0 = g[kbeg + k + 0] * W3[(kbeg + k + 0) * DD + c];
        float s1 = g[kbeg + k + 1] * W3[(kbeg + k + 1) * DD + c];
        float s2 = g[kbeg + k + 2] * W3[(kbeg + k + 2) * DD + c];
        float s3 = g[kbeg + k + 3] * W3[(kbeg + k + 3) * DD + c];
        s += (s0 + s1) + (s2 + s3);
    }
    part[p][c] = s;
    __syncthreads();
    if (p == 0)
        g_gvec[c] = part[0][c] + part[1][c] + part[2][c] + part[3][c] + b3[c];
}

// ---------------- kernel 4: edge scatter ----------------
__global__ void k_scatter(const int* __restrict__ snd, const int* __restrict__ rcv, int e) {
    int gw = (blockIdx.x * blockDim.x + threadIdx.x) >> 5;
    int lane = threadIdx.x & 31;
    if (gw >= e) return;
    int s = snd[gw];
    int r = rcv[gw];
    float4 v = ((const float4*)(g_conv + (long)s * DD))[lane];
    atomicAdd(((float4*)(g_agg + (long)r * DD)) + lane, v);
}

// ---------------- kernel 5: finalize h, accumulate an ----------------
#define RPB 64
__global__ void k_final(const float* __restrict__ nodes, float* __restrict__ out, int n) {
    __shared__ float red[256];
    int c    = threadIdx.x & (DD - 1);
    int half = threadIdx.x >> 7;
    int rs0  = blockIdx.x * RPB;
    int rs1  = min(rs0 + RPB, n);
    float gv = g_gvec[c];
    float local = 0.f;
    for (int r = rs0 + half; r < rs1; r += 2) {
        float rsn = rsqrtf(fmaxf(g_rdeg[r], 1.0f));
        long idx = (long)r * DD + c;
        float v = out[idx] + g_agg[idx] * rsn + gv;
        v = fmaxf(v, 0.f) + nodes[idx];
        out[idx] = v;
        local += v;
    }
    red[threadIdx.x] = local;
    __syncthreads();
    if (half == 0) atomicAdd(&g_an[c], red[c] + red[c + DD]);
}

// ---------------- kernel 6: global update ----------------
__global__ void k_gout(const float* __restrict__ g, const float* __restrict__ Wg,
                       const float* __restrict__ bg, float* __restrict__ out, long off) {
    __shared__ float part[4][DD];
    int c = threadIdx.x & (DD - 1);
    int p = threadIdx.x >> 7;
    float s = 0.f;
    int kbeg = p * 64;
#pragma unroll
    for (int k = 0; k < 64; k += 4) {
        int kk = kbeg + k;
        float x0 = (kk + 0 < DD) ? g_an[kk + 0] : g[kk + 0 - DD];
        float x1 = (kk + 1 < DD) ? g_an[kk + 1] : g[kk + 1 - DD];
        float x2 = (kk + 2 < DD) ? g_an[kk + 2] : g[kk + 2 - DD];
        float x3 = (kk + 3 < DD) ? g_an[kk + 3] : g[kk + 3 - DD];
        s += (x0 * Wg[(kk + 0) * DD + c] + x1 * Wg[(kk + 1) * DD + c])
           + (x2 * Wg[(kk + 2) * DD + c] + x3 * Wg[(kk + 3) * DD + c]);
    }
    part[p][c] = s;
    __syncthreads();
    if (p == 0) {
        float v = part[0][c] + part[1][c] + part[2][c] + part[3][c] + bg[c];
        out[off + c] = g[c] + fmaxf(v, 0.f);
    }
}

// ---------------- launch ----------------
extern "C" void kernel_launch(void* const* d_in, const int* in_sizes, int n_in,
                              void* d_out, int out_size) {
    const float* nodes    = (const float*)d_in[0];
    const float* globals_ = (const float*)d_in[1];
    const int*   senders  = (const int*)d_in[2];
    const int*   receivers= (const int*)d_in[3];
    const float* W1w = (const float*)d_in[4];
    const float* W1b = (const float*)d_in[5];
    const float* W2w = (const float*)d_in[6];
    const float* W2b = (const float*)d_in[7];
    const float* W3w = (const float*)d_in[8];
    const float* W3b = (const float*)d_in[9];
    const float* Wgw = (const float*)d_in[10];
    const float* Wgb = (const float*)d_in[11];
    float* out = (float*)d_out;

    int n = in_sizes[0] / DD;
    int e = in_sizes[2];

    cudaFuncSetAttribute(k_mm, cudaFuncAttributeMaxDynamicSharedMemorySize, SM_TOT);

    k_zero<<<1024, 256>>>(n);
    k_deg<<<(e + 255) / 256, 256>>>(senders, receivers, e);
    k_wconv<<<256, 256>>>(W1w, W2w);
    k_aconv<<<2048, 256>>>(nodes, n);
    k_mm<<<148, 512, SM_TOT>>>(W1b, W2b, out, n);
    k_gvec<<<1, 512>>>(globals_, W3w, W3b);
    k_scatter<<<(e + 7) / 8, 256>>>(senders, receivers, e);
    k_final<<<(n + RPB - 1) / RPB, 256>>>(nodes, out, n);
    k_gout<<<1, 512>>>(globals_, Wgw, Wgb, out, (long)n * DD);
}

// round 16
// speedup vs baseline: 2.1100x; 1.1101x over previous
#include <cuda_runtime.h>
#include <cuda_bf16.h>
#include <cstdint>

#define DD 128
#define MAXN 100000
#define MAXN_PAD 100032      // 1563 * 64
#define MAXE 640000

// ---------------- scratch (no allocations allowed) ----------------
__device__ float g_conv[(size_t)MAXN * DD];
__device__ float g_sdeg[MAXN];
__device__ float g_rdeg[MAXN];
__device__ float g_an  [DD];
__device__ float g_gvec[DD];
// W terms in [n][k] layout with pitch 136 elems (272 B): W1h, W1l, W2h, W2l
#define WPITCH 136
#define WTERM  (128 * WPITCH)          // 17408 elems = 34816 B
__device__ __nv_bfloat16 g_wstage[4 * WTERM];
// pre-converted A (bf16 hi/lo), contiguous [MAXN_PAD][128]
__device__ __nv_bfloat16 g_ahi[(size_t)MAXN_PAD * DD];
__device__ __nv_bfloat16 g_alo[(size_t)MAXN_PAD * DD];

// ---------------- PTX helpers ----------------
__device__ __forceinline__ uint32_t smem_u32(const void* p) {
    uint32_t a;
    asm("{ .reg .u64 t; cvta.to.shared.u64 t, %1; cvt.u32.u64 %0, t; }" : "=r"(a) : "l"(p));
    return a;
}
__device__ __forceinline__ void ldsm4(uint32_t* r, uint32_t addr) {
    asm volatile("ldmatrix.sync.aligned.m8n8.x4.shared.b16 {%0,%1,%2,%3}, [%4];"
                 : "=r"(r[0]), "=r"(r[1]), "=r"(r[2]), "=r"(r[3]) : "r"(addr));
}
__device__ __forceinline__ void mma16816(float* c, const uint32_t* a, uint32_t b0, uint32_t b1) {
    asm volatile("mma.sync.aligned.m16n8k16.row.col.f32.bf16.bf16.f32 "
                 "{%0,%1,%2,%3}, {%4,%5,%6,%7}, {%8,%9}, {%0,%1,%2,%3};"
                 : "+f"(c[0]), "+f"(c[1]), "+f"(c[2]), "+f"(c[3])
                 : "r"(a[0]), "r"(a[1]), "r"(a[2]), "r"(a[3]), "r"(b0), "r"(b1));
}
__device__ __forceinline__ void cp16(uint32_t dst, const void* src) {
    asm volatile("cp.async.cg.shared.global [%0], [%1], 16;" :: "r"(dst), "l"(src));
}
#define CP_COMMIT() asm volatile("cp.async.commit_group;" ::: "memory")
#define CP_WAIT1()  asm volatile("cp.async.wait_group 1;" ::: "memory")

// ---------------- kernel 1: zero small scratch ----------------
__global__ void k_zero(int n) {
    int tid = blockIdx.x * blockDim.x + threadIdx.x;
    int stride = gridDim.x * blockDim.x;
    for (int i = tid; i < n; i += stride) { g_sdeg[i] = 0.f; g_rdeg[i] = 0.f; }
    if (tid < DD) g_an[tid] = 0.f;
}

// ---------------- kernel 2: degrees + fused gvec (last block) ----------------
__global__ void k_degv(const int* __restrict__ snd, const int* __restrict__ rcv, int e,
                       const float* __restrict__ g, const float* __restrict__ W3,
                       const float* __restrict__ b3) {
    if (blockIdx.x == gridDim.x - 1) {
        __shared__ float part[2][DD];
        int c = threadIdx.x & (DD - 1);
        int p = threadIdx.x >> 7;          // 256 threads: 2 k-partitions
        float s = 0.f;
        int kbeg = p * 64;
#pragma unroll
        for (int k = 0; k < 64; k += 4) {
            float s0 = g[kbeg + k + 0] * W3[(kbeg + k + 0) * DD + c];
            float s1 = g[kbeg + k + 1] * W3[(kbeg + k + 1) * DD + c];
            float s2 = g[kbeg + k + 2] * W3[(kbeg + k + 2) * DD + c];
            float s3 = g[kbeg + k + 3] * W3[(kbeg + k + 3) * DD + c];
            s += (s0 + s1) + (s2 + s3);
        }
        part[p][c] = s;
        __syncthreads();
        if (p == 0) g_gvec[c] = part[0][c] + part[1][c] + b3[c];
        return;
    }
    int i = blockIdx.x * blockDim.x + threadIdx.x;
    if (i < e) {
        atomicAdd(&g_sdeg[snd[i]], 1.0f);
        atomicAdd(&g_rdeg[rcv[i]], 1.0f);
    }
}

// ---------------- kernel 2b: W -> bf16 hi/lo, [n][k] pitch-136 ----------------
__global__ void k_wconv(const float* __restrict__ W1, const float* __restrict__ W2) {
    int idx = blockIdx.x * blockDim.x + threadIdx.x;
    int mat = idx >> 14;
    int nn  = (idx >> 7) & 127;
    int k   = idx & 127;
    float w = (mat ? W2 : W1)[k * DD + nn];
    __nv_bfloat16 hi = __float2bfloat16(w);
    __nv_bfloat16 lo = __float2bfloat16(w - __bfloat162float(hi));
    int off = nn * WPITCH + k;
    g_wstage[(mat * 2 + 0) * WTERM + off] = hi;
    g_wstage[(mat * 2 + 1) * WTERM + off] = lo;
}

// ---------------- kernel 2c: A -> bf16 hi/lo (padded, contiguous) ----------------
__global__ void k_aconv(const float* __restrict__ nodes, int n) {
    long i4 = (long)blockIdx.x * blockDim.x + threadIdx.x;
    long tot = (long)MAXN_PAD * DD / 4;
    long stride = (long)gridDim.x * blockDim.x;
    for (; i4 < tot; i4 += stride) {
        long row = i4 >> 5;
        float4 v = make_float4(0.f, 0.f, 0.f, 0.f);
        if (row < n) v = ((const float4*)nodes)[i4];
        __nv_bfloat16 hx = __float2bfloat16(v.x), hy = __float2bfloat16(v.y);
        __nv_bfloat16 hz = __float2bfloat16(v.z), hw = __float2bfloat16(v.w);
        __nv_bfloat16 lx = __float2bfloat16(v.x - __bfloat162float(hx));
        __nv_bfloat16 ly = __float2bfloat16(v.y - __bfloat162float(hy));
        __nv_bfloat16 lz = __float2bfloat16(v.z - __bfloat162float(hz));
        __nv_bfloat16 lw = __float2bfloat16(v.w - __bfloat162float(hw));
        uint2 hp, lp;
        hp.x = ((uint32_t)__bfloat16_as_ushort(hy) << 16) | __bfloat16_as_ushort(hx);
        hp.y = ((uint32_t)__bfloat16_as_ushort(hw) << 16) | __bfloat16_as_ushort(hz);
        lp.x = ((uint32_t)__bfloat16_as_ushort(ly) << 16) | __bfloat16_as_ushort(lx);
        lp.y = ((uint32_t)__bfloat16_as_ushort(lw) << 16) | __bfloat16_as_ushort(lz);
        ((uint2*)g_ahi)[i4] = hp;
        ((uint2*)g_alo)[i4] = lp;
    }
}

// ---------------- kernel 3: split-bf16 dual GEMM, 512 thr, cp.async double-buffer ----
#define SM_B1   0
#define SM_B2   512
#define SM_A    1024
#define ABUF    34816
#define SM_W    (SM_A + 2 * ABUF)
#define SM_TOT  (SM_W + 4 * 34816)    // 209920 B

__device__ __forceinline__ void load_tile_a(uint32_t sb, int tile, int buf, int tid) {
    uint32_t base = sb + SM_A + (uint32_t)buf * ABUF;
    long row0 = (long)tile * 64;
#pragma unroll
    for (int j = 0; j < 4; j++) {
        int c = tid + j * 512;
        int term = c >> 10;
        int rr   = (c >> 4) & 63;
        int col  = c & 15;
        uint32_t dst = base + (uint32_t)term * 17408 + (uint32_t)rr * 272 + (uint32_t)(col << 4);
        const char* srcb = (const char*)(term ? g_alo : g_ahi)
                         + ((row0 + rr) << 8) + (col << 4);
        cp16(dst, srcb);
    }
}

__global__ void __launch_bounds__(512, 1) k_mm(
    const float* __restrict__ b1, const float* __restrict__ b2,
    float* __restrict__ outH, int n)
{
    extern __shared__ char smem[];
    uint32_t sb = smem_u32(smem);
    int tid = threadIdx.x;
    int warp = tid >> 5, lane = tid & 31;
    int wn = warp & 7;
    int wm = warp >> 3;
    int ntiles = (n + 63) >> 6;

    {
        const float4* src = (const float4*)g_wstage;
        float4* dst = (float4*)(smem + SM_W);
        for (int i = tid; i < 8704; i += 512) dst[i] = src[i];
        if (tid < 32) {
            ((float4*)(smem + SM_B1))[tid] = ((const float4*)b1)[tid];
            ((float4*)(smem + SM_B2))[tid] = ((const float4*)b2)[tid];
        }
    }

    const float* b1s = (const float*)(smem + SM_B1);
    const float* b2s = (const float*)(smem + SM_B2);

    uint32_t lrow = lane & 15;
    uint32_t khb  = (lane >> 4) << 4;
    uint32_t aoff = lrow * 272 + khb + (uint32_t)wm * (32 * 272);
    uint32_t boff = ((uint32_t)wn * 16 + lrow) * 272 + khb;

    int qrow = lane >> 2;
    int qcol = (lane & 3) << 1;

    int tile = blockIdx.x;
    if (tile < ntiles) load_tile_a(sb, tile, 0, tid);
    CP_COMMIT();
    int bufc = 0;
    __syncthreads();

    for (; tile < ntiles; tile += gridDim.x) {
        int nexttile = tile + gridDim.x;
        if (nexttile < ntiles) load_tile_a(sb, nexttile, bufc ^ 1, tid);
        CP_COMMIT();
        CP_WAIT1();
        __syncthreads();

        uint32_t abase = sb + SM_A + (uint32_t)bufc * ABUF + aoff;

        float acc[2][2][2][4];
#pragma unroll
        for (int m = 0; m < 2; m++)
#pragma unroll
            for (int nt = 0; nt < 2; nt++)
#pragma unroll
                for (int mt = 0; mt < 2; mt++)
#pragma unroll
                    for (int c = 0; c < 4; c++) acc[m][nt][mt][c] = 0.f;

#pragma unroll
        for (int ks = 0; ks < 8; ks++) {
            uint32_t kb = (uint32_t)ks * 32;
            uint32_t bf[4][4];
#pragma unroll
            for (int t = 0; t < 4; t++)
                ldsm4(bf[t], sb + SM_W + (uint32_t)t * 34816 + boff + kb);
#pragma unroll
            for (int m = 0; m < 2; m++) {
                uint32_t ah[4], al[4];
                uint32_t ab = abase + (uint32_t)m * (16 * 272) + kb;
                ldsm4(ah, ab);
                ldsm4(al, ab + 17408);
                mma16816(acc[m][0][0], ah, bf[0][0], bf[0][2]);
                mma16816(acc[m][1][0], ah, bf[0][1], bf[0][3]);
                mma16816(acc[m][0][0], ah, bf[1][0], bf[1][2]);
                mma16816(acc[m][1][0], ah, bf[1][1], bf[1][3]);
                mma16816(acc[m][0][0], al, bf[0][0], bf[0][2]);
                mma16816(acc[m][1][0], al, bf[0][1], bf[0][3]);
                mma16816(acc[m][0][1], ah, bf[2][0], bf[2][2]);
                mma16816(acc[m][1][1], ah, bf[2][1], bf[2][3]);
                mma16816(acc[m][0][1], ah, bf[3][0], bf[3][2]);
                mma16816(acc[m][1][1], ah, bf[3][1], bf[3][3]);
                mma16816(acc[m][0][1], al, bf[2][0], bf[2][2]);
                mma16816(acc[m][1][1], al, bf[2][1], bf[2][3]);
            }
        }
        __syncthreads();

        int row0 = tile << 6;
#pragma unroll
        for (int m = 0; m < 2; m++) {
#pragma unroll
            for (int h = 0; h < 2; h++) {
                int grow = row0 + wm * 32 + m * 16 + qrow + h * 8;
                if (grow >= n) continue;
                float f = rsqrtf(fmaxf(g_sdeg[grow], 1.0f));
                long gb = (long)grow * DD;
#pragma unroll
                for (int nt = 0; nt < 2; nt++) {
                    int col = wn * 16 + nt * 8 + qcol;
                    float2 o1, o2;
                    o1.x = acc[m][nt][0][2 * h + 0] + b1s[col + 0];
                    o1.y = acc[m][nt][0][2 * h + 1] + b1s[col + 1];
                    o2.x = (acc[m][nt][1][2 * h + 0] + b2s[col + 0]) * f;
                    o2.y = (acc[m][nt][1][2 * h + 1] + b2s[col + 1]) * f;
                    *(float2*)(outH + gb + col)   = o1;
                    *(float2*)(g_conv + gb + col) = o2;
                }
            }
        }
        bufc ^= 1;
    }
}

// ---------------- kernel 4: edge scatter, fused recv-norm,直接 into out ----------------
__global__ void k_scatter(const int* __restrict__ snd, const int* __restrict__ rcv,
                          float* __restrict__ out, int e) {
    int gw = (blockIdx.x * blockDim.x + threadIdx.x) >> 5;
    int lane = threadIdx.x & 31;
    if (gw >= e) return;
    int s = snd[gw];
    int r = rcv[gw];
    float rs = rsqrtf(fmaxf(g_rdeg[r], 1.0f));
    float4 v = ((const float4*)(g_conv + (long)s * DD))[lane];
    v.x *= rs; v.y *= rs; v.z *= rs; v.w *= rs;
    atomicAdd(((float4*)(out + (long)r * DD)) + lane, v);
}

// ---------------- kernel 5: finalize h, accumulate an ----------------
#define RPB 64
__global__ void k_final(const float* __restrict__ nodes, float* __restrict__ out, int n) {
    __shared__ float red[256];
    int c    = threadIdx.x & (DD - 1);
    int half = threadIdx.x >> 7;
    int rs0  = blockIdx.x * RPB;
    int rs1  = min(rs0 + RPB, n);
    float gv = g_gvec[c];
    float local = 0.f;
    for (int r = rs0 + half; r < rs1; r += 2) {
        long idx = (long)r * DD + c;
        float v = out[idx] + gv;
        v = fmaxf(v, 0.f) + nodes[idx];
        out[idx] = v;
        local += v;
    }
    red[threadIdx.x] = local;
    __syncthreads();
    if (half == 0) atomicAdd(&g_an[c], red[c] + red[c + DD]);
}

// ---------------- kernel 6: global update ----------------
__global__ void k_gout(const float* __restrict__ g, const float* __restrict__ Wg,
                       const float* __restrict__ bg, float* __restrict__ out, long off) {
    __shared__ float part[4][DD];
    int c = threadIdx.x & (DD - 1);
    int p = threadIdx.x >> 7;
    float s = 0.f;
    int kbeg = p * 64;
#pragma unroll
    for (int k = 0; k < 64; k += 4) {
        int kk = kbeg + k;
        float x0 = (kk + 0 < DD) ? g_an[kk + 0] : g[kk + 0 - DD];
        float x1 = (kk + 1 < DD) ? g_an[kk + 1] : g[kk + 1 - DD];
        float x2 = (kk + 2 < DD) ? g_an[kk + 2] : g[kk + 2 - DD];
        float x3 = (kk + 3 < DD) ? g_an[kk + 3] : g[kk + 3 - DD];
        s += (x0 * Wg[(kk + 0) * DD + c] + x1 * Wg[(kk + 1) * DD + c])
           + (x2 * Wg[(kk + 2) * DD + c] + x3 * Wg[(kk + 3) * DD + c]);
    }
    part[p][c] = s;
    __syncthreads();
    if (p == 0) {
        float v = part[0][c] + part[1][c] + part[2][c] + part[3][c] + bg[c];
        out[off + c] = g[c] + fmaxf(v, 0.f);
    }
}

// ---------------- launch ----------------
extern "C" void kernel_launch(void* const* d_in, const int* in_sizes, int n_in,
                              void* d_out, int out_size) {
    const float* nodes    = (const float*)d_in[0];
    const float* globals_ = (const float*)d_in[1];
    const int*   senders  = (const int*)d_in[2];
    const int*   receivers= (const int*)d_in[3];
    const float* W1w = (const float*)d_in[4];
    const float* W1b = (const float*)d_in[5];
    const float* W2w = (const float*)d_in[6];
    const float* W2b = (const float*)d_in[7];
    const float* W3w = (const float*)d_in[8];
    const float* W3b = (const float*)d_in[9];
    const float* Wgw = (const float*)d_in[10];
    const float* Wgb = (const float*)d_in[11];
    float* out = (float*)d_out;

    int n = in_sizes[0] / DD;
    int e = in_sizes[2];

    cudaFuncSetAttribute(k_mm, cudaFuncAttributeMaxDynamicSharedMemorySize, SM_TOT);

    k_zero<<<128, 256>>>(n);
    k_degv<<<(e + 255) / 256 + 1, 256>>>(senders, receivers, e, globals_, W3w, W3b);
    k_wconv<<<256, 256>>>(W1w, W2w);
    k_aconv<<<2048, 256>>>(nodes, n);
    k_mm<<<148, 512, SM_TOT>>>(W1b, W2b, out, n);
    k_scatter<<<(e + 7) / 8, 256>>>(senders, receivers, out, e);
    k_final<<<(n + RPB - 1) / RPB, 256>>>(nodes, out, n);
    k_gout<<<1, 512>>>(globals_, Wgw, Wgb, out, (long)n * DD);
}